// round 17
// baseline (speedup 1.0000x reference)
#include <cuda_runtime.h>
#include <cuda_fp16.h>

#define G     512
#define GG    (G * G)
#define C     48
#define CP    64                  // padded channels per texel (128B rows)
#define PPB   64                  // points per block in sampler
#define GRP   8                   // lanes per point (6 active + 2 pad)
#define THREADS 512               // PPB * GRP
#define TT    128                 // texels per plane-transpose tile
#define LTT   64                  // texels per line-transpose tile

// fp16 scratch, padded layout [texel][64ch] (planes 100.7 MB, lines 197 KB)
__device__ __half g_planeH[3ULL * GG * CP];
__device__ __half g_lineH[3ULL * G * CP];

// ---------------------------------------------------------------------------
// Shared-memory overlays
// ---------------------------------------------------------------------------
struct TileSM {                       // transpose path: 24.8 KB
    float tile[C][TT + 1];
};
struct SampSM {                       // sampler path: 13.8 KB
    int   t[PPB];
    int   lz[PPB];
    float wx[PPB];
    float wy[PPB];
    float wz[PPB];
    float feat[C][PPB + 1];
};
#define SMEM_BYTES (sizeof(TileSM) > sizeof(SampSM) ? sizeof(TileSM) : sizeof(SampSM))

// ---------------------------------------------------------------------------
// Plane-transpose body (512 threads): in [C][GG] fp32 -> out [GG][CP] fp16
// Only the first 12 uint2 (48 ch) of each padded 16-uint2 row are written.
// ---------------------------------------------------------------------------
__device__ __forceinline__ void tpose_body(const float* __restrict__ in,
                                           __half* __restrict__ out,
                                           int blk, TileSM* sm) {
    const int j0  = blk * TT;
    const int tid = threadIdx.x;

    #pragma unroll
    for (int k = 0; k < 3; k++) {                 // 1536 float4 loads
        int i = tid + k * THREADS;
        int c = i >> 5;                           // /(TT/4)=32
        int v = i & 31;
        float4 f = __ldg(reinterpret_cast<const float4*>(in + (size_t)c * GG + j0) + v);
        sm->tile[c][4 * v + 0] = f.x;
        sm->tile[c][4 * v + 1] = f.y;
        sm->tile[c][4 * v + 2] = f.z;
        sm->tile[c][4 * v + 3] = f.w;
    }
    __syncthreads();

    uint2* o2 = reinterpret_cast<uint2*>(out) + (size_t)j0 * (CP / 4);
    #pragma unroll
    for (int k = 0; k < 3; k++) {                 // 1536 uint2 stores
        int i  = tid + k * THREADS;
        int j  = i / 12;
        int c4 = i % 12;
        __half2 h0 = __float22half2_rn(make_float2(sm->tile[4 * c4 + 0][j], sm->tile[4 * c4 + 1][j]));
        __half2 h1 = __float22half2_rn(make_float2(sm->tile[4 * c4 + 2][j], sm->tile[4 * c4 + 3][j]));
        uint2 u;
        u.x = *reinterpret_cast<unsigned*>(&h0);
        u.y = *reinterpret_cast<unsigned*>(&h1);
        o2[(size_t)j * (CP / 4) + c4] = u;
    }
}

// ---------------------------------------------------------------------------
// Line-transpose body (512 threads): in [C][G] -> out [G][CP], 64 texels/blk
// ---------------------------------------------------------------------------
__device__ __forceinline__ void tpose_line_body(const float* __restrict__ in,
                                                __half* __restrict__ out,
                                                int blk, TileSM* sm) {
    const int j0  = blk * LTT;
    const int tid = threadIdx.x;

    #pragma unroll
    for (int k = 0; k < 6; k++) {                 // 3072 scalar loads
        int i = tid + k * THREADS;
        int c = i >> 6;
        int j = i & 63;
        sm->tile[c][j] = in[c * G + j0 + j];
    }
    __syncthreads();

    uint2* o2 = reinterpret_cast<uint2*>(out) + (size_t)j0 * (CP / 4);
    for (int i = tid; i < LTT * 12; i += THREADS) {   // 768 uint2 stores
        int j  = i / 12;
        int c4 = i % 12;
        __half2 h0 = __float22half2_rn(make_float2(sm->tile[4 * c4 + 0][j], sm->tile[4 * c4 + 1][j]));
        __half2 h1 = __float22half2_rn(make_float2(sm->tile[4 * c4 + 2][j], sm->tile[4 * c4 + 3][j]));
        uint2 u;
        u.x = *reinterpret_cast<unsigned*>(&h0);
        u.y = *reinterpret_cast<unsigned*>(&h1);
        o2[(size_t)j * (CP / 4) + c4] = u;
    }
}

// ---------------------------------------------------------------------------
// Sampler body for mode M. Warp = 4 points x 8 lanes (lanes 6,7 idle in ph1).
// M=0: gx=x gy=y gz=z ; M=1: gx=x gy=z gz=y ; M=2: gx=y gy=z gz=x
// ---------------------------------------------------------------------------
template <int M>
__device__ __forceinline__ void sample_body(const float* __restrict__ xyz,
                                            float* __restrict__ out, int N,
                                            int blk, SampSM* sm) {
    const int n0  = blk * PPB;
    const int tid = threadIdx.x;

    // ---- Phase 0: per-point indices & weights ----
    if (tid < PPB) {
        int n = n0 + tid;
        float x = 0.f, y = 0.f, z = 0.f;
        if (n < N) {
            x = xyz[3 * n + 0];
            y = xyz[3 * n + 1];
            z = xyz[3 * n + 2];
        }
        const float gx = (M == 2) ? y : x;
        const float gy = (M == 0) ? y : z;
        const float gz = (M == 0) ? z : ((M == 1) ? y : x);

        float ix   = (gx + 1.0f) * 0.5f * (float)(G - 1);
        float iy   = (gy + 1.0f) * 0.5f * (float)(G - 1);
        float ix0f = fminf(fmaxf(floorf(ix), 0.0f), (float)(G - 1));
        float iy0f = fminf(fmaxf(floorf(iy), 0.0f), (float)(G - 1));
        int ix0 = (int)ix0f;
        int iy0 = (int)iy0f;
        sm->t[tid]  = iy0 * G + ix0;
        sm->wx[tid] = ix - ix0f;
        sm->wy[tid] = iy - iy0f;

        float iz   = (gz + 1.0f) * 0.5f * (float)(G - 1);
        float iz0f = fminf(fmaxf(floorf(iz), 0.0f), (float)(G - 1));
        int iz0 = (int)iz0f;
        sm->lz[tid] = iz0;
        sm->wz[tid] = iz - iz0f;
    }
    __syncthreads();

    // ---- Phase 1: gather fp16 (line-aligned 128B rows), interpolate fp32 ----
    {
        const int c8 = tid & (GRP - 1);    // 0..7
        const int p  = tid >> 3;           // 0..63
        if (c8 < 6) {
            const __half* P = g_planeH + (size_t)M * GG * CP;
            const __half* L = g_lineH + (size_t)M * G * CP;

            const int   t   = sm->t[p];
            const int   ix0 = t & (G - 1);
            const int   iy0 = t >> 9;
            const int   dx  = (ix0 < G - 1) ? 1 : 0;
            const int   dy  = (iy0 < G - 1) ? G : 0;
            const float wx  = sm->wx[p];
            const float wy  = sm->wy[p];
            const int   lz  = sm->lz[p];
            const int   dz  = (lz < G - 1) ? 1 : 0;
            const float wz  = sm->wz[p];
            const int   co  = c8 * 8;

            uint4 q00 = __ldg(reinterpret_cast<const uint4*>(P + (size_t)t * CP + co));
            uint4 q01 = __ldg(reinterpret_cast<const uint4*>(P + (size_t)(t + dx) * CP + co));
            uint4 q10 = __ldg(reinterpret_cast<const uint4*>(P + (size_t)(t + dy) * CP + co));
            uint4 q11 = __ldg(reinterpret_cast<const uint4*>(P + (size_t)(t + dy + dx) * CP + co));
            uint4 ql0 = __ldg(reinterpret_cast<const uint4*>(L + (size_t)lz * CP + co));
            uint4 ql1 = __ldg(reinterpret_cast<const uint4*>(L + (size_t)(lz + dz) * CP + co));

            const unsigned* u00 = reinterpret_cast<const unsigned*>(&q00);
            const unsigned* u01 = reinterpret_cast<const unsigned*>(&q01);
            const unsigned* u10 = reinterpret_cast<const unsigned*>(&q10);
            const unsigned* u11 = reinterpret_cast<const unsigned*>(&q11);
            const unsigned* ul0 = reinterpret_cast<const unsigned*>(&ql0);
            const unsigned* ul1 = reinterpret_cast<const unsigned*>(&ql1);

            #pragma unroll
            for (int q = 0; q < 4; q++) {
                float2 a = __half22float2(*reinterpret_cast<const __half2*>(&u00[q]));
                float2 b = __half22float2(*reinterpret_cast<const __half2*>(&u01[q]));
                float2 c = __half22float2(*reinterpret_cast<const __half2*>(&u10[q]));
                float2 d = __half22float2(*reinterpret_cast<const __half2*>(&u11[q]));
                float2 e = __half22float2(*reinterpret_cast<const __half2*>(&ul0[q]));
                float2 f = __half22float2(*reinterpret_cast<const __half2*>(&ul1[q]));

                float2 top, bot, pl, ln;
                top.x = fmaf(wx, b.x - a.x, a.x);
                top.y = fmaf(wx, b.y - a.y, a.y);
                bot.x = fmaf(wx, d.x - c.x, c.x);
                bot.y = fmaf(wx, d.y - c.y, c.y);
                pl.x  = fmaf(wy, bot.x - top.x, top.x);
                pl.y  = fmaf(wy, bot.y - top.y, top.y);
                ln.x  = fmaf(wz, f.x - e.x, e.x);
                ln.y  = fmaf(wz, f.y - e.y, e.y);

                sm->feat[co + 2 * q + 0][p] = pl.x * ln.x;
                sm->feat[co + 2 * q + 1][p] = pl.y * ln.y;
            }
        }
    }
    __syncthreads();

    // ---- Phase 2: coalesced fp32 stores (512 threads, 48 rows) ----
    {
        const int p  = tid & (PPB - 1);
        const int r0 = tid >> 6;         // 0..7
        const int n  = n0 + p;
        if (n < N) {
            #pragma unroll
            for (int i = 0; i < 6; i++) {
                const int r = r0 + i * 8;    // 0..47
                out[(size_t)r * N + n] = sm->feat[r][p];
            }
        }
    }
}

// ---------------------------------------------------------------------------
// Fused kernel: blocks [0,nS) sample mode M; blocks [nS,nS+nT) transpose
// plane (M+1). Sampler blocks lead so wave-1 isn't pure transpose.
// ---------------------------------------------------------------------------
template <int M>
__global__ __launch_bounds__(THREADS)
void fused_kernel(const float* __restrict__ xyz,
                  const float* __restrict__ plane_in,
                  float* __restrict__ out, int N, int nS) {
    __shared__ __align__(16) char smbuf[SMEM_BYTES];
    if ((int)blockIdx.x < nS) {
        sample_body<M>(xyz, out, N, blockIdx.x,
                       reinterpret_cast<SampSM*>(smbuf));
    } else {
        tpose_body(plane_in, g_planeH + (size_t)(M + 1) * GG * CP,
                   blockIdx.x - nS, reinterpret_cast<TileSM*>(smbuf));
    }
}

// First kernel: plane-0 transpose + all three line transposes in one grid.
__global__ __launch_bounds__(THREADS)
void tpose0_kernel(const float* __restrict__ p0,
                   const float* __restrict__ l0,
                   const float* __restrict__ l1,
                   const float* __restrict__ l2, int nT) {
    __shared__ __align__(16) char smbuf[SMEM_BYTES];
    TileSM* sm = reinterpret_cast<TileSM*>(smbuf);
    const int b = (int)blockIdx.x;
    if (b < nT) {
        tpose_body(p0, g_planeH, b, sm);
    } else {
        const int lb  = b - nT;                  // 0..23
        const int pid = lb >> 3;                 // 0..2
        const float* in = (pid == 0) ? l0 : (pid == 1) ? l1 : l2;
        tpose_line_body(in, g_lineH + (size_t)pid * G * CP, lb & 7, sm);
    }
}

// ---------------------------------------------------------------------------
extern "C" void kernel_launch(void* const* d_in, const int* in_sizes, int n_in,
                              void* d_out, int out_size) {
    const float* xyz = (const float*)d_in[0];
    const float* p0  = (const float*)d_in[1];
    const float* p1  = (const float*)d_in[2];
    const float* p2  = (const float*)d_in[3];
    const float* l0  = (const float*)d_in[4];
    const float* l1  = (const float*)d_in[5];
    const float* l2  = (const float*)d_in[6];
    const int N = in_sizes[0] / 3;
    float* out = (float*)d_out;

    const int nT = GG / TT;                  // 2048 plane-transpose blocks
    const int nL = 3 * (G / LTT);            // 24 line-transpose blocks
    const int nS = (N + PPB - 1) / PPB;      // 8192 sampler blocks

    tpose0_kernel<<<nT + nL, THREADS>>>(p0, l0, l1, l2, nT);

    fused_kernel<0><<<nS + nT, THREADS>>>(xyz, p1, out + 0ULL * C * N, N, nS);
    fused_kernel<1><<<nS + nT, THREADS>>>(xyz, p2, out + 1ULL * C * N, N, nS);
    fused_kernel<2><<<nS, THREADS>>>(xyz, nullptr, out + 2ULL * C * N, N, nS);
}